// round 7
// baseline (speedup 1.0000x reference)
#include <cuda_runtime.h>
#include <math.h>

#define GRID_H   48
#define NPTS     2304
#define NCH      16
#define IPB      2         // i's per block
#define SUBW     4         // warps per i
#define NOFF     277       // in-circle window offsets (dr^2+dc^2 <= 88)
#define MAXE     112       // per-warp compacted list capacity
#define XSTRIDE  36864     // NPTS*NCH
#define NGRP     1152      // NPTS/IPB
#define GRIDN    740       // 148 SMs * 5 resident blocks

// Phase A + spline + compaction, warp-local. NR = rounds for this warp.
template<int NR>
__device__ __forceinline__ int phase_a(
    int lane, float inv_h, int ri, int ci, float xi, float yi,
    const int* __restrict__ drv, const int* __restrict__ dcv,
    const float* __restrict__ distv, const int* __restrict__ joffv,
    const float4* __restrict__ wva,            // per-warp (w2,w3,v,a) rows
    const float* __restrict__ sS, float b2, int ibase,
    float2* __restrict__ wjRow)
{
    const float inv47 = 1.0f / 47.0f;
    float xj[NR], yj[NR], acc[NR];
#pragma unroll
    for (int r = 0; r < NR; r++) {
        xj[r] = fmaf((float)drv[r], inv47, xi);
        yj[r] = fmaf((float)dcv[r], inv47, yi);
        acc[r] = 0.0f;
    }
#pragma unroll
    for (int k = 0; k < 32; k++) {
        float4 w = wva[k];    // LDS.128 broadcast
#pragma unroll
        for (int r = 0; r < NR; r++) {
            float t = fmaf(yj[r], w.y, fmaf(xj[r], w.x, w.w));
            acc[r] = fmaf(w.z, fmaxf(t, 0.0f), acc[r]);
        }
    }
    const float CKNOT = 1.0f / (1.0f / 15.0f + 1e-8f);
    int cnt = 0;
#pragma unroll
    for (int r = 0; r < NR; r++) {
        int rj = ri + drv[r];
        int cj = ci + dcv[r];
        bool ok = ((unsigned)rj < GRID_H) && ((unsigned)cj < GRID_H);
        if (NR == 3 && r == 2) ok = ok && (lane < NOFF - 256);  // partial round
        unsigned m = __ballot_sync(0xffffffffu, ok);
        if (ok) {
            float rr  = fminf(distv[r] * inv_h, 1.0f);
            int   idx = min((int)(rr * 15.0f), 14);
            float wr  = (rr - (float)idx * (1.0f / 15.0f)) * CKNOT;
            float s0  = sS[idx];
            float psi = fmaf(wr, sS[idx + 1] - s0, s0);
            float w   = (acc[r] + b2) * psi;
            int  pos  = cnt + __popc(m & ((1u << lane) - 1u));
            wjRow[pos] = make_float2(w, __int_as_float(ibase + joffv[r]));
        }
        cnt += __popc(m);
    }
    return cnt;
}

__global__ __launch_bounds__(256, 5)
void si_blocks_kernel(const float* __restrict__ x,
                      const float* __restrict__ phi_w1, const float* __restrict__ phi_b1,
                      const float* __restrict__ phi_w2, const float* __restrict__ phi_b2,
                      const float* __restrict__ h_w1,  const float* __restrict__ h_b1,
                      const float* __restrict__ h_w2,  const float* __restrict__ h_b2,
                      const float* __restrict__ S_m,
                      float* __restrict__ out)
{
    __shared__ float  sW0[32], sW1[32], sB1[32];
    __shared__ float  sHW1a[32], sHW1b[32], sHB1[32], sHW2[32];
    __shared__ float  sS[16], sDist[89];
    __shared__ float  sB2v, sHB2v;
    __shared__ int    sOff[288];                 // packed (dr+9)<<5 | (dc+9)
    __shared__ float4 sWVA[8][32];               // per-warp (w2,w3,v,a) rows
    __shared__ float2 sWJ[8][MAXE];              // per-warp compacted lists
    __shared__ int    sCnt[2][8];
    __shared__ float4 sPart[2][IPB][SUBW][8];

    const int tid  = threadIdx.x;
    const int warp = tid >> 5;
    const int lane = tid & 31;
    const int p    = warp >> 2;
    const int sub  = warp & 3;
    const float inv47 = 1.0f / 47.0f;

    // ---- one-time init ----
    if (tid < 16) sS[tid] = S_m[tid];
    if (tid >= 32 && tid < 64) {
        int l = tid - 32;
        sW0[l] = phi_w1[l]; sW1[l] = phi_w1[32 + l]; sB1[l] = phi_b1[l];
        sHW1a[l] = h_w1[l]; sHW1b[l] = h_w1[32 + l];
        sHB1[l] = h_b1[l];  sHW2[l] = h_w2[l];
    }
    if (tid == 16) sB2v  = phi_b2[0];
    if (tid == 17) sHB2v = h_b2[0];
    if (tid >= 64 && tid < 153) sDist[tid - 64] = sqrtf((float)(tid - 64)) * inv47;
    if (warp == 7) {   // compact in-circle offsets (deterministic order)
        int cnt = 0;
        for (int rr = 0; rr < 12; rr++) {
            int cand = lane + rr * 32;
            int q = cand / 19;
            int dr = q - 9, dc = cand - q * 19 - 9;
            bool ok = (cand < 361) && (dr * dr + dc * dc <= 88);
            unsigned m = __ballot_sync(0xffffffffu, ok);
            if (ok) sOff[cnt + __popc(m & ((1u << lane) - 1u))] = ((dr + 9) << 5) | (dc + 9);
            cnt += __popc(m);
        }
    }
    __syncthreads();

    // ---- persistent per-lane phi weights (k = lane) ----
    const float w2L = phi_w1[64 + lane];
    const float w3L = phi_w1[96 + lane];
    const float vL  = phi_w2[lane];

    // ---- per-warp window geometry (persistent) ----
    int   drv[3], dcv[3], joffv[3];
    float distv[3];
#pragma unroll
    for (int r = 0; r < 3; r++) {
        int slot = lane + 32 * (sub + 4 * r);
        int pk = (slot < NOFF) ? sOff[slot] : ((9 << 5) | 9);
        int dr = (pk >> 5) - 9, dc = (pk & 31) - 9;
        drv[r] = dr; dcv[r] = dc;
        distv[r] = sDist[dr * dr + dc * dc];
        joffv[r] = (dr * GRID_H + dc) * NCH;
    }

    const int n2 = lane >> 3;
    const int bb = (lane >> 2) & 1;
    const int qq = lane & 3;
    const float* xq = x + bb * XSTRIDE + qq * 4;
    const float4* wva = sWVA[warp];
    float2* wjRow = sWJ[warp];

    int parity = 0;
    for (int grp = blockIdx.x; grp < NGRP; grp += GRIDN) {
        const int   i  = grp * IPB + p;
        const int   ri = i / GRID_H;
        const int   ci = i - ri * GRID_H;
        const float xi = (float)ri * inv47;
        const float yi = (float)ci * inv47;

        // h_net (warp-local, redundant; no barrier)
        float hz = fmaxf(fmaf(xi, sHW1a[lane], fmaf(yi, sHW1b[lane], sHB1[lane])), 0.0f)
                   * sHW2[lane];
#pragma unroll
        for (int o = 16; o; o >>= 1) hz += __shfl_xor_sync(0xffffffffu, hz, o);
        hz += sHB2v;
        float hval  = fmaxf(hz, 0.0f) + log1pf(expf(-fabsf(hz)));
        float inv_h = 1.0f / (hval + 1e-6f);

        // per-i phi row: (w2,w3,v,a) for k = lane, one STS.128
        float aL = fmaf(xi, sW0[lane], fmaf(yi, sW1[lane], sB1[lane]));
        sWVA[warp][lane] = make_float4(w2L, w3L, vL, aL);
        __syncwarp();

        // Phase A + compact
        int cnt;
        if (sub == 0)
            cnt = phase_a<3>(lane, inv_h, ri, ci, xi, yi, drv, dcv, distv, joffv,
                             wva, sS, sB2v, i * NCH, wjRow);
        else
            cnt = phase_a<2>(lane, inv_h, ri, ci, xi, yi, drv, dcv, distv, joffv,
                             wva, sS, sB2v, i * NCH, wjRow);
        if (lane < 12) wjRow[cnt + lane] = make_float2(0.0f, __int_as_float(0));
        if (lane == 0) sCnt[parity][warp] = cnt;
        __syncwarp();

        // Phase B: 4 neighbors x 2 batches x 16 ch per warp-iter, prefetched
        const int cnt4 = (cnt + 3) & ~3;
        float4 acc = make_float4(0.f, 0.f, 0.f, 0.f);
        float2 wj = wjRow[n2];
        for (int t = 0; t < cnt4; t += 4) {
            float2 nxt = wjRow[t + 4 + n2];
            const float4 v = *reinterpret_cast<const float4*>(xq + __float_as_int(wj.y));
            acc.x = fmaf(wj.x, v.x, acc.x);
            acc.y = fmaf(wj.x, v.y, acc.y);
            acc.z = fmaf(wj.x, v.z, acc.z);
            acc.w = fmaf(wj.x, v.w, acc.w);
            wj = nxt;
        }
#pragma unroll
        for (int o = 8; o <= 16; o <<= 1) {
            acc.x += __shfl_xor_sync(0xffffffffu, acc.x, o);
            acc.y += __shfl_xor_sync(0xffffffffu, acc.y, o);
            acc.z += __shfl_xor_sync(0xffffffffu, acc.z, o);
            acc.w += __shfl_xor_sync(0xffffffffu, acc.w, o);
        }
        if (lane < 8) sPart[parity][p][sub][lane] = acc;

        // sync only the 4 warps of this i
        asm volatile("bar.sync %0, 128;" :: "r"(p + 1) : "memory");

        if (sub == 0 && lane < 8) {
            float4 s0 = sPart[parity][p][0][lane];
            float4 s1 = sPart[parity][p][1][lane];
            float4 s2 = sPart[parity][p][2][lane];
            float4 s3 = sPart[parity][p][3][lane];
            int tot = sCnt[parity][4*p] + sCnt[parity][4*p+1]
                    + sCnt[parity][4*p+2] + sCnt[parity][4*p+3];
            float sc = 1.0f / (float)tot;
            float4 o;
            o.x = (s0.x + s1.x + s2.x + s3.x) * sc;
            o.y = (s0.y + s1.y + s2.y + s3.y) * sc;
            o.z = (s0.z + s1.z + s2.z + s3.z) * sc;
            o.w = (s0.w + s1.w + s2.w + s3.w) * sc;
            *reinterpret_cast<float4*>(out + bb * XSTRIDE + i * NCH + qq * 4) = o;
        }
        parity ^= 1;
    }
}

extern "C" void kernel_launch(void* const* d_in, const int* in_sizes, int n_in,
                              void* d_out, int out_size)
{
    const float* x      = (const float*)d_in[0];
    const float* phi_w1 = (const float*)d_in[1];
    const float* phi_b1 = (const float*)d_in[2];
    const float* phi_w2 = (const float*)d_in[3];
    const float* phi_b2 = (const float*)d_in[4];
    const float* h_w1   = (const float*)d_in[5];
    const float* h_b1   = (const float*)d_in[6];
    const float* h_w2   = (const float*)d_in[7];
    const float* h_b2   = (const float*)d_in[8];
    const float* S_m    = (const float*)d_in[9];
    float* out = (float*)d_out;

    si_blocks_kernel<<<GRIDN, 256>>>(
        x, phi_w1, phi_b1, phi_w2, phi_b2,
        h_w1, h_b1, h_w2, h_b2, S_m, out);
}

// round 8
// speedup vs baseline: 1.1233x; 1.1233x over previous
#include <cuda_runtime.h>
#include <math.h>

#define GRID_H   48
#define NPTS     2304
#define NCH      16
#define IPB      2         // i's per block
#define SUBW     4         // warps per i
#define NOFF     277       // in-circle window offsets (dr^2+dc^2 <= 88)
#define MAXE     112       // per-warp compacted list capacity
#define XSTRIDE  36864     // NPTS*NCH
#define NGRP     1152      // NPTS/IPB
#define GRIDN    576       // each block does exactly NGRP/GRIDN = 2 groups

// Phase A + spline + compaction, warp-local. NR = rounds for this warp.
template<int NR>
__device__ __forceinline__ int phase_a(
    int lane, float inv_h, int ri, int ci, float xi, float yi,
    const int* __restrict__ drv, const int* __restrict__ dcv,
    const float* __restrict__ distv, const int* __restrict__ joffv,
    const float4* __restrict__ wva,            // per-warp (w2,w3,v,a) rows
    const float* __restrict__ sS, float b2, int ibase,
    float2* __restrict__ wjRow)
{
    const float inv47 = 1.0f / 47.0f;
    float xj[NR], yj[NR], acc[NR];
#pragma unroll
    for (int r = 0; r < NR; r++) {
        xj[r] = fmaf((float)drv[r], inv47, xi);
        yj[r] = fmaf((float)dcv[r], inv47, yi);
        acc[r] = 0.0f;
    }
#pragma unroll
    for (int k = 0; k < 32; k++) {
        float4 w = wva[k];    // LDS.128 broadcast
#pragma unroll
        for (int r = 0; r < NR; r++) {
            float t = fmaf(yj[r], w.y, fmaf(xj[r], w.x, w.w));
            acc[r] = fmaf(w.z, fmaxf(t, 0.0f), acc[r]);
        }
    }
    const float CKNOT = 1.0f / (1.0f / 15.0f + 1e-8f);
    int cnt = 0;
#pragma unroll
    for (int r = 0; r < NR; r++) {
        int rj = ri + drv[r];
        int cj = ci + dcv[r];
        bool ok = ((unsigned)rj < GRID_H) && ((unsigned)cj < GRID_H);
        if (NR == 3 && r == 2) ok = ok && (lane < NOFF - 256);  // partial round
        unsigned m = __ballot_sync(0xffffffffu, ok);
        if (ok) {
            float rr  = fminf(distv[r] * inv_h, 1.0f);
            int   idx = min((int)(rr * 15.0f), 14);
            float wr  = (rr - (float)idx * (1.0f / 15.0f)) * CKNOT;
            float s0  = sS[idx];
            float psi = fmaf(wr, sS[idx + 1] - s0, s0);
            float w   = (acc[r] + b2) * psi;
            int  pos  = cnt + __popc(m & ((1u << lane) - 1u));
            wjRow[pos] = make_float2(w, __int_as_float(ibase + joffv[r]));
        }
        cnt += __popc(m);
    }
    return cnt;
}

__global__ __launch_bounds__(256, 4)
void si_blocks_kernel(const float* __restrict__ x,
                      const float* __restrict__ phi_w1, const float* __restrict__ phi_b1,
                      const float* __restrict__ phi_w2, const float* __restrict__ phi_b2,
                      const float* __restrict__ h_w1,  const float* __restrict__ h_b1,
                      const float* __restrict__ h_w2,  const float* __restrict__ h_b2,
                      const float* __restrict__ S_m,
                      float* __restrict__ out)
{
    __shared__ float  sW0[32], sW1[32], sB1[32];
    __shared__ float  sHW1a[32], sHW1b[32], sHB1[32], sHW2[32];
    __shared__ float  sS[16], sDist[89];
    __shared__ float  sB2v, sHB2v;
    __shared__ int    sOff[288];                 // packed (dr+9)<<5 | (dc+9)
    __shared__ float4 sWVA[8][32];               // per-warp (w2,w3,v,a) rows
    __shared__ float2 sWJ[8][MAXE];              // per-warp compacted lists
    __shared__ int    sCnt[2][8];
    __shared__ float4 sPart[2][IPB][SUBW][8];

    const int tid  = threadIdx.x;
    const int warp = tid >> 5;
    const int lane = tid & 31;
    const int p    = warp >> 2;
    const int sub  = warp & 3;
    const float inv47 = 1.0f / 47.0f;

    // ---- one-time init ----
    if (tid < 16) sS[tid] = S_m[tid];
    if (tid >= 32 && tid < 64) {
        int l = tid - 32;
        sW0[l] = phi_w1[l]; sW1[l] = phi_w1[32 + l]; sB1[l] = phi_b1[l];
        sHW1a[l] = h_w1[l]; sHW1b[l] = h_w1[32 + l];
        sHB1[l] = h_b1[l];  sHW2[l] = h_w2[l];
    }
    if (tid == 16) sB2v  = phi_b2[0];
    if (tid == 17) sHB2v = h_b2[0];
    if (tid >= 64 && tid < 153) sDist[tid - 64] = sqrtf((float)(tid - 64)) * inv47;
    if (warp == 7) {   // compact in-circle offsets (deterministic order)
        int cnt = 0;
        for (int rr = 0; rr < 12; rr++) {
            int cand = lane + rr * 32;
            int q = cand / 19;
            int dr = q - 9, dc = cand - q * 19 - 9;
            bool ok = (cand < 361) && (dr * dr + dc * dc <= 88);
            unsigned m = __ballot_sync(0xffffffffu, ok);
            if (ok) sOff[cnt + __popc(m & ((1u << lane) - 1u))] = ((dr + 9) << 5) | (dc + 9);
            cnt += __popc(m);
        }
    }
    __syncthreads();

    // ---- persistent per-lane phi weights (k = lane) ----
    const float w2L = phi_w1[64 + lane];
    const float w3L = phi_w1[96 + lane];
    const float vL  = phi_w2[lane];

    // ---- per-warp window geometry (persistent) ----
    int   drv[3], dcv[3], joffv[3];
    float distv[3];
#pragma unroll
    for (int r = 0; r < 3; r++) {
        int slot = lane + 32 * (sub + 4 * r);
        int pk = (slot < NOFF) ? sOff[slot] : ((9 << 5) | 9);
        int dr = (pk >> 5) - 9, dc = (pk & 31) - 9;
        drv[r] = dr; dcv[r] = dc;
        distv[r] = sDist[dr * dr + dc * dc];
        joffv[r] = (dr * GRID_H + dc) * NCH;
    }

    const int n2 = lane >> 3;
    const int bb = (lane >> 2) & 1;
    const int qq = lane & 3;
    const float* xq = x + bb * XSTRIDE + qq * 4;
    const float4* wva = sWVA[warp];
    float2* wjRow = sWJ[warp];

    int parity = 0;
#pragma unroll
    for (int w = 0; w < NGRP / GRIDN; w++) {
        const int grp = blockIdx.x + w * GRIDN;
        const int   i  = grp * IPB + p;
        const int   ri = i / GRID_H;
        const int   ci = i - ri * GRID_H;
        const float xi = (float)ri * inv47;
        const float yi = (float)ci * inv47;

        // h_net (warp-local, redundant; no barrier)
        float hz = fmaxf(fmaf(xi, sHW1a[lane], fmaf(yi, sHW1b[lane], sHB1[lane])), 0.0f)
                   * sHW2[lane];
#pragma unroll
        for (int o = 16; o; o >>= 1) hz += __shfl_xor_sync(0xffffffffu, hz, o);
        hz += sHB2v;
        float hval  = fmaxf(hz, 0.0f) + log1pf(expf(-fabsf(hz)));
        float inv_h = 1.0f / (hval + 1e-6f);

        // per-i phi row: (w2,w3,v,a) for k = lane, one STS.128
        float aL = fmaf(xi, sW0[lane], fmaf(yi, sW1[lane], sB1[lane]));
        sWVA[warp][lane] = make_float4(w2L, w3L, vL, aL);
        __syncwarp();

        // Phase A + compact
        int cnt;
        if (sub == 0)
            cnt = phase_a<3>(lane, inv_h, ri, ci, xi, yi, drv, dcv, distv, joffv,
                             wva, sS, sB2v, i * NCH, wjRow);
        else
            cnt = phase_a<2>(lane, inv_h, ri, ci, xi, yi, drv, dcv, distv, joffv,
                             wva, sS, sB2v, i * NCH, wjRow);
        if (lane < 12) wjRow[cnt + lane] = make_float2(0.0f, __int_as_float(0));
        if (lane == 0) sCnt[parity][warp] = cnt;
        __syncwarp();

        // Phase B: 4 neighbors x 2 batches x 16 ch per warp-iter, prefetched
        const int cnt4 = (cnt + 3) & ~3;
        float4 acc = make_float4(0.f, 0.f, 0.f, 0.f);
        float2 wj = wjRow[n2];
        for (int t = 0; t < cnt4; t += 4) {
            float2 nxt = wjRow[t + 4 + n2];
            const float4 v = *reinterpret_cast<const float4*>(xq + __float_as_int(wj.y));
            acc.x = fmaf(wj.x, v.x, acc.x);
            acc.y = fmaf(wj.x, v.y, acc.y);
            acc.z = fmaf(wj.x, v.z, acc.z);
            acc.w = fmaf(wj.x, v.w, acc.w);
            wj = nxt;
        }
#pragma unroll
        for (int o = 8; o <= 16; o <<= 1) {
            acc.x += __shfl_xor_sync(0xffffffffu, acc.x, o);
            acc.y += __shfl_xor_sync(0xffffffffu, acc.y, o);
            acc.z += __shfl_xor_sync(0xffffffffu, acc.z, o);
            acc.w += __shfl_xor_sync(0xffffffffu, acc.w, o);
        }
        if (lane < 8) sPart[parity][p][sub][lane] = acc;

        // sync only the 4 warps of this i
        asm volatile("bar.sync %0, 128;" :: "r"(p + 1) : "memory");

        if (sub == 0 && lane < 8) {
            float4 s0 = sPart[parity][p][0][lane];
            float4 s1 = sPart[parity][p][1][lane];
            float4 s2 = sPart[parity][p][2][lane];
            float4 s3 = sPart[parity][p][3][lane];
            int tot = sCnt[parity][4*p] + sCnt[parity][4*p+1]
                    + sCnt[parity][4*p+2] + sCnt[parity][4*p+3];
            float sc = 1.0f / (float)tot;
            float4 o;
            o.x = (s0.x + s1.x + s2.x + s3.x) * sc;
            o.y = (s0.y + s1.y + s2.y + s3.y) * sc;
            o.z = (s0.z + s1.z + s2.z + s3.z) * sc;
            o.w = (s0.w + s1.w + s2.w + s3.w) * sc;
            *reinterpret_cast<float4*>(out + bb * XSTRIDE + i * NCH + qq * 4) = o;
        }
        parity ^= 1;
    }
}

extern "C" void kernel_launch(void* const* d_in, const int* in_sizes, int n_in,
                              void* d_out, int out_size)
{
    const float* x      = (const float*)d_in[0];
    const float* phi_w1 = (const float*)d_in[1];
    const float* phi_b1 = (const float*)d_in[2];
    const float* phi_w2 = (const float*)d_in[3];
    const float* phi_b2 = (const float*)d_in[4];
    const float* h_w1   = (const float*)d_in[5];
    const float* h_b1   = (const float*)d_in[6];
    const float* h_w2   = (const float*)d_in[7];
    const float* h_b2   = (const float*)d_in[8];
    const float* S_m    = (const float*)d_in[9];
    float* out = (float*)d_out;

    si_blocks_kernel<<<GRIDN, 256>>>(
        x, phi_w1, phi_b1, phi_w2, phi_b2,
        h_w1, h_b1, h_w2, h_b2, S_m, out);
}